// round 6
// baseline (speedup 1.0000x reference)
#include <cuda_runtime.h>
#include <cuda_bf16.h>
#include <cstddef>

// Problem constants
#define BATCH 2
#define SEQ   2048
#define EMB   1024
#define NH    16
#define HD    64
#define INNER (NH * HD)     // 1024
#define MTOT  (BATCH * SEQ) // 4096

// Scratch buffers (allocation-free rule: __device__ globals)
__device__ float g_q[BATCH * NH * SEQ * HD];
__device__ float g_k[BATCH * NH * SEQ * HD];
__device__ float g_v[BATCH * NH * SEQ * HD];
__device__ float g_ctx[BATCH * SEQ * INNER];

// ---------------------------------------------------------------------------
// tf32 helpers
// ---------------------------------------------------------------------------
__device__ __forceinline__ unsigned f2tf32(float f) {
    unsigned u;
    asm("cvt.rna.tf32.f32 %0, %1;" : "=r"(u) : "f"(f));
    return u;
}

__device__ __forceinline__ void mma_tf32(
    float& c0, float& c1, float& c2, float& c3,
    unsigned a0, unsigned a1, unsigned a2, unsigned a3,
    unsigned b0, unsigned b1)
{
    asm volatile(
        "mma.sync.aligned.m16n8k8.row.col.f32.tf32.tf32.f32 "
        "{%0,%1,%2,%3}, {%4,%5,%6,%7}, {%8,%9}, {%0,%1,%2,%3};"
        : "+f"(c0), "+f"(c1), "+f"(c2), "+f"(c3)
        : "r"(a0), "r"(a1), "r"(a2), "r"(a3), "r"(b0), "r"(b1));
}

__device__ __forceinline__ void cp16(void* smem, const void* gmem) {
    unsigned a = (unsigned)__cvta_generic_to_shared(smem);
    asm volatile("cp.async.cg.shared.global [%0], [%1], 16;"
                 :: "r"(a), "l"(gmem));
}

// ---------------------------------------------------------------------------
// tf32 tensor-core NT GEMM v3: C[m,n] = sum_k X[m,k] * W[n,k]
// Fixed shape M=4096, N=1024, K=1024.
// Block tile 128x256, BK=32, 256 threads (8 warps), warp tile 64x64 (2x4).
// grid.z selects operand set (QKV fused); mode 1 scatters to (b,h,s,d).
// ---------------------------------------------------------------------------
#define GS 36
__global__ void __launch_bounds__(256, 1) gemm3_tc_kernel(
    const float* __restrict__ X0, const float* __restrict__ X1,
    const float* __restrict__ X2,
    const float* __restrict__ W0, const float* __restrict__ W1,
    const float* __restrict__ W2,
    float* __restrict__ O0, float* __restrict__ O1, float* __restrict__ O2,
    const float* __restrict__ bias, int mode)
{
    __shared__ unsigned As[128 * GS];
    __shared__ unsigned Bs[256 * GS];

    const int z = blockIdx.z;
    const float* X = (z == 0) ? X0 : (z == 1) ? X1 : X2;
    const float* W = (z == 0) ? W0 : (z == 1) ? W1 : W2;
    float*       O = (z == 0) ? O0 : (z == 1) ? O1 : O2;

    const int K = EMB;          // 1024
    const int N = INNER;        // 1024

    const int tid  = threadIdx.x;
    const int warp = tid >> 5;
    const int lane = tid & 31;
    const int g    = lane >> 2;
    const int tig  = lane & 3;

    const int row0 = blockIdx.y * 128;
    const int col0 = blockIdx.x * 256;
    const int wm   = (warp >> 2) * 64;   // 0 or 64
    const int wn   = (warp & 3) * 64;    // 0,64,128,192

    // staging assignment
    const int arow = tid >> 1;                 // 0..127
    const int ac0  = (tid & 1) * 16;           // 0 or 16
    const int brow = tid;                      // 0..255

    float acc[4][8][4] = {};                   // [mi][ni][c]
    float4 xv[4], wv[8];

    const int ktiles = K >> 5;                 // 32

    // Prologue: load tile 0
    #pragma unroll
    for (int i = 0; i < 4; i++)
        xv[i] = *(const float4*)&X[(size_t)(row0 + arow) * K + ac0 + i * 4];
    #pragma unroll
    for (int i = 0; i < 8; i++)
        wv[i] = *(const float4*)&W[(size_t)(col0 + brow) * K + i * 4];

    for (int t = 0; t < ktiles; t++) {
        // store staged tile to smem with tf32 convert
        #pragma unroll
        for (int i = 0; i < 4; i++) {
            unsigned* p = &As[arow * GS + ac0 + i * 4];
            p[0] = f2tf32(xv[i].x); p[1] = f2tf32(xv[i].y);
            p[2] = f2tf32(xv[i].z); p[3] = f2tf32(xv[i].w);
        }
        #pragma unroll
        for (int i = 0; i < 8; i++) {
            unsigned* p = &Bs[brow * GS + i * 4];
            p[0] = f2tf32(wv[i].x); p[1] = f2tf32(wv[i].y);
            p[2] = f2tf32(wv[i].z); p[3] = f2tf32(wv[i].w);
        }
        __syncthreads();

        // prefetch next tile
        if (t + 1 < ktiles) {
            int k0 = (t + 1) << 5;
            #pragma unroll
            for (int i = 0; i < 4; i++)
                xv[i] = *(const float4*)&X[(size_t)(row0 + arow) * K + k0 + ac0 + i * 4];
            #pragma unroll
            for (int i = 0; i < 8; i++)
                wv[i] = *(const float4*)&W[(size_t)(col0 + brow) * K + k0 + i * 4];
        }

        // 4 k8-steps
        #pragma unroll
        for (int kk = 0; kk < 4; kk++) {
            int k0 = kk << 3;
            unsigned a[4][4], b[8][2];
            #pragma unroll
            for (int mi = 0; mi < 4; mi++) {
                int rb = wm + mi * 16;
                a[mi][0] = As[(rb + g)     * GS + k0 + tig];
                a[mi][1] = As[(rb + g + 8) * GS + k0 + tig];
                a[mi][2] = As[(rb + g)     * GS + k0 + tig + 4];
                a[mi][3] = As[(rb + g + 8) * GS + k0 + tig + 4];
            }
            #pragma unroll
            for (int ni = 0; ni < 8; ni++) {
                int cb = wn + ni * 8;
                b[ni][0] = Bs[(cb + g) * GS + k0 + tig];
                b[ni][1] = Bs[(cb + g) * GS + k0 + tig + 4];
            }
            #pragma unroll
            for (int mi = 0; mi < 4; mi++)
                #pragma unroll
                for (int ni = 0; ni < 8; ni++)
                    mma_tf32(acc[mi][ni][0], acc[mi][ni][1],
                             acc[mi][ni][2], acc[mi][ni][3],
                             a[mi][0], a[mi][1], a[mi][2], a[mi][3],
                             b[ni][0], b[ni][1]);
        }
        __syncthreads();
    }

    // Epilogue
    #pragma unroll
    for (int mi = 0; mi < 4; mi++) {
        #pragma unroll
        for (int half = 0; half < 2; half++) {
            int m = row0 + wm + mi * 16 + g + half * 8;
            #pragma unroll
            for (int ni = 0; ni < 8; ni++) {
                int n = col0 + wn + ni * 8 + tig * 2;
                float v0 = acc[mi][ni][half * 2 + 0];
                float v1 = acc[mi][ni][half * 2 + 1];
                if (mode == 0) {
                    v0 += bias[n]; v1 += bias[n + 1];
                    *(float2*)&O[(size_t)m * N + n] = make_float2(v0, v1);
                } else {
                    int b_  = m >> 11;
                    int s_  = m & 2047;
                    int h_  = n >> 6;
                    int d_  = n & 63;
                    size_t base = (((size_t)(b_ * NH + h_)) * SEQ + s_) * HD;
                    *(float2*)&O[base + d_] = make_float2(v0, v1);
                }
            }
        }
    }
}

// ---------------------------------------------------------------------------
// Tensor-core flash attention (tf32 mma). Unchanged from R5.
// ---------------------------------------------------------------------------
#define KST 68
#define VST 72
#define PST 72
#define FLASH_SMEM ((64*KST + 64*VST + 64*PST + 64) * 4)

__global__ void __launch_bounds__(128) flash_tc_kernel(
    const int* __restrict__ pmask,   // (B, SEQ) int32
    const int* __restrict__ fmask,   // scalar int32
    float* __restrict__ ctx)         // (B, SEQ, INNER)
{
    extern __shared__ float sm[];
    float* Ks      = sm;                    // 64*KST
    float* Vs      = Ks + 64 * KST;         // 64*VST
    float* Ps      = Vs + 64 * VST;         // 64*PST
    float* maskadd = Ps + 64 * PST;         // 64

    const int tid  = threadIdx.x;
    const int warp = tid >> 5;
    const int lane = tid & 31;
    const int g    = lane >> 2;
    const int tig  = lane & 3;
    const int swc  = g & 4;                 // XOR swizzle for Ps

    const int qt = gridDim.x - 1 - blockIdx.x;  // heavy tiles first
    const int bh = blockIdx.y;
    const int b  = bh >> 4;
    const int h  = bh & 15;
    const int fut = fmask[0];

    const float* Qg = g_q + (size_t)bh * SEQ * HD;
    const float* Kg = g_k + (size_t)bh * SEQ * HD;
    const float* Vg = g_v + (size_t)bh * SEQ * HD;

    // Q a-fragments, scale 1/sqrt(64)=0.125 folded in.
    const int r0 = qt * 64 + warp * 16;
    unsigned qa[8][4];
    #pragma unroll
    for (int kc = 0; kc < 8; kc++) {
        qa[kc][0] = f2tf32(0.125f * Qg[(size_t)(r0 + g)     * HD + kc * 8 + tig]);
        qa[kc][1] = f2tf32(0.125f * Qg[(size_t)(r0 + g + 8) * HD + kc * 8 + tig]);
        qa[kc][2] = f2tf32(0.125f * Qg[(size_t)(r0 + g)     * HD + kc * 8 + tig + 4]);
        qa[kc][3] = f2tf32(0.125f * Qg[(size_t)(r0 + g + 8) * HD + kc * 8 + tig + 4]);
    }

    float om0 = -1e30f, om1 = -1e30f;   // running max (rows g, g+8)
    float ol0 = 0.0f,   ol1 = 0.0f;     // running sum
    float oacc[8][4] = {};              // O c-frags: [d-block][c0..c3]

    const int rowg0 = r0 + g;
    const int rowg1 = r0 + g + 8;

    const int ktmax = fut ? qt : (SEQ / 64 - 1);
    for (int kt = 0; kt <= ktmax; kt++) {
        __syncthreads();   // prior-tile frag reads complete

        // K/V tile -> smem via cp.async (16B each, 8+8 per thread)
        #pragma unroll
        for (int i = 0; i < 8; i++) {
            int idx = tid + i * 128;       // 0..1023
            int r = idx >> 4;
            int c = (idx & 15) << 2;
            cp16(&Ks[r * KST + c], &Kg[(size_t)(kt * 64 + r) * HD + c]);
            cp16(&Vs[r * VST + c], &Vg[(size_t)(kt * 64 + r) * HD + c]);
        }
        if (tid < 64)
            maskadd[tid] = pmask[b * SEQ + kt * 64 + tid] ? 0.0f : -1e30f;
        asm volatile("cp.async.wait_all;" ::: "memory");
        __syncthreads();

        // ---- S = Q K^T  (8 col-blocks x 8 k-steps) ----
        float s[8][4];
        #pragma unroll
        for (int j = 0; j < 8; j++) { s[j][0]=0; s[j][1]=0; s[j][2]=0; s[j][3]=0; }
        #pragma unroll
        for (int j = 0; j < 8; j++) {
            #pragma unroll
            for (int ks = 0; ks < 8; ks++) {
                unsigned b0 = __float_as_uint(Ks[(8*j + g) * KST + 8*ks + tig]);
                unsigned b1 = __float_as_uint(Ks[(8*j + g) * KST + 8*ks + tig + 4]);
                mma_tf32(s[j][0], s[j][1], s[j][2], s[j][3],
                         qa[ks][0], qa[ks][1], qa[ks][2], qa[ks][3], b0, b1);
            }
        }

        // ---- masks ----
        const bool diag = fut && (kt == qt);
        #pragma unroll
        for (int j = 0; j < 8; j++) {
            int c0 = 8*j + 2*tig;
            float ma0 = maskadd[c0];
            float ma1 = maskadd[c0 + 1];
            s[j][0] += ma0; s[j][1] += ma1;
            s[j][2] += ma0; s[j][3] += ma1;
            if (diag) {
                int gc0 = kt * 64 + c0;
                if (gc0     > rowg0) s[j][0] = -1e30f;
                if (gc0 + 1 > rowg0) s[j][1] = -1e30f;
                if (gc0     > rowg1) s[j][2] = -1e30f;
                if (gc0 + 1 > rowg1) s[j][3] = -1e30f;
            }
        }

        // ---- online softmax (frag space; reduce over tig via shfl) ----
        float mx0 = -1e30f, mx1 = -1e30f;
        #pragma unroll
        for (int j = 0; j < 8; j++) {
            mx0 = fmaxf(mx0, fmaxf(s[j][0], s[j][1]));
            mx1 = fmaxf(mx1, fmaxf(s[j][2], s[j][3]));
        }
        mx0 = fmaxf(mx0, __shfl_xor_sync(0xffffffffu, mx0, 1));
        mx0 = fmaxf(mx0, __shfl_xor_sync(0xffffffffu, mx0, 2));
        mx1 = fmaxf(mx1, __shfl_xor_sync(0xffffffffu, mx1, 1));
        mx1 = fmaxf(mx1, __shfl_xor_sync(0xffffffffu, mx1, 2));

        float mn0 = fmaxf(om0, mx0);
        float mn1 = fmaxf(om1, mx1);
        float cf0 = __expf(om0 - mn0);
        float cf1 = __expf(om1 - mn1);
        om0 = mn0; om1 = mn1;

        __syncwarp();   // prior-tile Ps a-frag reads complete (warp-private)

        float sum0 = 0.0f, sum1 = 0.0f;
        #pragma unroll
        for (int j = 0; j < 8; j++) {
            float p0 = __expf(s[j][0] - mn0);
            float p1 = __expf(s[j][1] - mn0);
            float p2 = __expf(s[j][2] - mn1);
            float p3 = __expf(s[j][3] - mn1);
            sum0 += p0 + p1;
            sum1 += p2 + p3;
            int cs = 8*j + ((2*tig) ^ swc);      // swizzled col
            float2 lo = make_float2(__uint_as_float(f2tf32(p0)),
                                    __uint_as_float(f2tf32(p1)));
            float2 hi = make_float2(__uint_as_float(f2tf32(p2)),
                                    __uint_as_float(f2tf32(p3)));
            *(float2*)&Ps[(warp*16 + g)     * PST + cs] = lo;
            *(float2*)&Ps[(warp*16 + g + 8) * PST + cs] = hi;
        }
        sum0 += __shfl_xor_sync(0xffffffffu, sum0, 1);
        sum0 += __shfl_xor_sync(0xffffffffu, sum0, 2);
        sum1 += __shfl_xor_sync(0xffffffffu, sum1, 1);
        sum1 += __shfl_xor_sync(0xffffffffu, sum1, 2);
        ol0 = ol0 * cf0 + sum0;
        ol1 = ol1 * cf1 + sum1;

        // rescale O accumulators
        #pragma unroll
        for (int j = 0; j < 8; j++) {
            oacc[j][0] *= cf0; oacc[j][1] *= cf0;
            oacc[j][2] *= cf1; oacc[j][3] *= cf1;
        }
        __syncwarp();   // P strip visible to whole warp

        // ---- load P a-frags (swizzled, conflict-free) ----
        unsigned pa[8][4];
        #pragma unroll
        for (int kc = 0; kc < 8; kc++) {
            int cA = 8*kc + (tig ^ swc);
            int cB = 8*kc + ((tig + 4) ^ swc);
            pa[kc][0] = __float_as_uint(Ps[(warp*16 + g)     * PST + cA]);
            pa[kc][1] = __float_as_uint(Ps[(warp*16 + g + 8) * PST + cA]);
            pa[kc][2] = __float_as_uint(Ps[(warp*16 + g)     * PST + cB]);
            pa[kc][3] = __float_as_uint(Ps[(warp*16 + g + 8) * PST + cB]);
        }

        // ---- O += P V  (8 d-blocks x 8 k-steps) ----
        #pragma unroll
        for (int j = 0; j < 8; j++) {
            #pragma unroll
            for (int ks = 0; ks < 8; ks++) {
                unsigned b0 = __float_as_uint(Vs[(8*ks + tig)     * VST + 8*j + g]);
                unsigned b1 = __float_as_uint(Vs[(8*ks + tig + 4) * VST + 8*j + g]);
                mma_tf32(oacc[j][0], oacc[j][1], oacc[j][2], oacc[j][3],
                         pa[ks][0], pa[ks][1], pa[ks][2], pa[ks][3], b0, b1);
            }
        }
    }

    // ---- epilogue: normalize + store ----
    float inv0 = (ol0 > 0.0f) ? (1.0f / ol0) : 0.0f;
    float inv1 = (ol1 > 0.0f) ? (1.0f / ol1) : 0.0f;
    #pragma unroll
    for (int j = 0; j < 8; j++) {
        int n = h * HD + 8*j + 2*tig;
        size_t base0 = ((size_t)b * SEQ + rowg0) * INNER + n;
        size_t base1 = ((size_t)b * SEQ + rowg1) * INNER + n;
        *(float2*)&ctx[base0] = make_float2(oacc[j][0] * inv0, oacc[j][1] * inv0);
        *(float2*)&ctx[base1] = make_float2(oacc[j][2] * inv1, oacc[j][3] * inv1);
    }
}

// ---------------------------------------------------------------------------
// Launch
// ---------------------------------------------------------------------------
extern "C" void kernel_launch(void* const* d_in, const int* in_sizes, int n_in,
                              void* d_out, int out_size)
{
    const float* q  = (const float*)d_in[0];
    const float* k  = (const float*)d_in[1];
    const float* v  = (const float*)d_in[2];
    const int*   pm = (const int*)d_in[3];
    const int*   fm = (const int*)d_in[4];
    const float* Wq = (const float*)d_in[5];
    const float* Wk = (const float*)d_in[6];
    const float* Wv = (const float*)d_in[7];
    const float* Wo = (const float*)d_in[8];
    const float* bo = (const float*)d_in[9];
    float* out = (float*)d_out;

    float *gq, *gk, *gv, *gctx;
    cudaGetSymbolAddress((void**)&gq,   g_q);
    cudaGetSymbolAddress((void**)&gk,   g_k);
    cudaGetSymbolAddress((void**)&gv,   g_v);
    cudaGetSymbolAddress((void**)&gctx, g_ctx);

    dim3 gblk(256);

    // Fused QKV projections -> (B,H,S,D) layout (tf32 tensor cores)
    gemm3_tc_kernel<<<dim3(INNER / 256, MTOT / 128, 3), gblk>>>(
        q, k, v, Wq, Wk, Wv, gq, gk, gv, nullptr, 1);

    // Flash attention (tf32 tensor cores)
    cudaFuncSetAttribute(flash_tc_kernel,
                         cudaFuncAttributeMaxDynamicSharedMemorySize, FLASH_SMEM);
    flash_tc_kernel<<<dim3(SEQ / 64, BATCH * NH), 128, FLASH_SMEM>>>(pm, fm, gctx);

    // Output projection + bias (tf32 tensor cores)
    gemm3_tc_kernel<<<dim3(EMB / 256, MTOT / 128, 1), gblk>>>(
        gctx, gctx, gctx, Wo, Wo, Wo, out, out, out, bo, 0);
}